// round 12
// baseline (speedup 1.0000x reference)
#include <cuda_runtime.h>
#include <cstdint>

// ---------------- problem constants ----------------
#define HW   196
#define BB   8
#define SEQ  32
#define DD   768
#define DH   192
#define HALF 96                  // DH/2
#define NSEQ (BB*HW)             // 1568
#define MTOT (NSEQ*SEQ)          // 50176

// ---------------- scratch (__device__ globals) ------------------------------
__device__ float g_xd [MTOT*DH];
__device__ float g_q  [MTOT*DH];
__device__ float g_k  [MTOT*DH];
__device__ float g_v  [MTOT*DH];
__device__ float g_ret[MTOT*DH];

// tf32-split weights, natural [K][N] layout
__device__ float g_w1h[DD*DH], g_w1l[DD*DH];
__device__ float g_wqh[DH*DH], g_wql[DH*DH];
__device__ float g_wkh[DH*DH], g_wkl[DH*DH];
__device__ float g_wvh[DH*DH], g_wvl[DH*DH];
__device__ float g_w2h[DH*DD], g_w2l[DH*DD];

// xPos tables: [t (0..31)][p (0..95)]
__device__ float g_cos_u[SEQ*HALF];
__device__ float g_sin_u[SEQ*HALF];
__device__ float g_cos_d[SEQ*HALF];
__device__ float g_sin_d[SEQ*HALF];

__device__ __forceinline__ int x_row_of(int m) {
    int q  = m >> 5;
    int t  = m & 31;
    int bi = q / HW;
    int hi = q - bi * HW;
    return hi * (BB * SEQ) + bi * SEQ + t;
}

// ---------------- helpers ----------------------------------------------------
__device__ __forceinline__ float f2tf32(float x) {
    uint32_t u;
    asm("cvt.rna.tf32.f32 %0, %1;" : "=r"(u) : "f"(x));
    return __uint_as_float(u);
}
__device__ __forceinline__ void cpasync16(uint32_t s, const void* g) {
    asm volatile("cp.async.ca.shared.global [%0], [%1], 16;" :: "r"(s), "l"(g) : "memory");
}
#define CP_COMMIT() asm volatile("cp.async.commit_group;" ::: "memory")
#define CP_WAIT0()  asm volatile("cp.async.wait_group 0;" ::: "memory")

__device__ __forceinline__ void mma8(float* d, const uint32_t* a, uint32_t b0, uint32_t b1) {
    asm volatile(
        "mma.sync.aligned.m16n8k8.row.col.f32.tf32.tf32.f32 "
        "{%0,%1,%2,%3}, {%4,%5,%6,%7}, {%8,%9}, {%0,%1,%2,%3};"
        : "+f"(d[0]), "+f"(d[1]), "+f"(d[2]), "+f"(d[3])
        : "r"(a[0]), "r"(a[1]), "r"(a[2]), "r"(a[3]), "r"(b0), "r"(b1));
}

// ---------------- prep: weight tf32 split + xPos tables ---------------------
__device__ __forceinline__ void w_split(const float* __restrict__ W,
                                        float* __restrict__ Wh, float* __restrict__ Wl, int idx) {
    float v = W[idx];
    float h = f2tf32(v);
    Wh[idx] = h;
    Wl[idx] = f2tf32(v - h);
}

__global__ void k_prep(const float* __restrict__ W1, const float* __restrict__ WQ,
                       const float* __restrict__ WK, const float* __restrict__ WV,
                       const float* __restrict__ W2) {
    int idx = blockIdx.x * blockDim.x + threadIdx.x;
    if (idx < DD*DH) { w_split(W1, g_w1h, g_w1l, idx); return; }
    idx -= DD*DH;
    if (idx < DH*DH) { w_split(WQ, g_wqh, g_wql, idx); return; }
    idx -= DH*DH;
    if (idx < DH*DH) { w_split(WK, g_wkh, g_wkl, idx); return; }
    idx -= DH*DH;
    if (idx < DH*DH) { w_split(WV, g_wvh, g_wvl, idx); return; }
    idx -= DH*DH;
    if (idx < DH*DD) { w_split(W2, g_w2h, g_w2l, idx); return; }
    idx -= DH*DD;
    if (idx < SEQ*HALF) {
        int t = idx / HALF, p = idx % HALF;
        double base = (2.0 * p + 0.4 * (double)DH) / (1.4 * (double)DH);
        double sc_u = pow(base, (double)t / 512.0);
        double sc_d = 1.0 / sc_u;
        double invf = pow(10000.0, -(double)p / (double)HALF);
        double ang  = (double)t * invf;
        double s = sin(ang), c = cos(ang);
        g_cos_u[idx] = (float)(c * sc_u);
        g_sin_u[idx] = (float)(s * sc_u);
        g_cos_d[idx] = (float)(c * sc_d);
        g_sin_d[idx] = (float)(s * sc_d);
    }
}

// ---------------- 3xTF32 mma.sync GEMM, BM=64 BN=192 BK=16 ------------------
// 128 threads = 4 warps in a 2(M) x 2(N) grid; warp tile 32 rows x 96 cols.
// Each B fragment feeds 2 m16 MMAs -> LDS/HMMA = 0.89 (was 1.44).
// MODE 0: A gathered from x; +bias then fused LayerNorm (cross-warp smem red.)
// MODE 1/2: xPos up/down epilogue   MODE 3: plain
// MODE 4: +bias +x residual (gathered rows), gathered store
#define AP 20
#define BP 200
#define A_BUF (64*AP)            // 1280
#define B_BUF (16*BP)            // 3200
#define SMEM_FLOATS (4*A_BUF + 4*B_BUF)   // 17920 floats = 71680 B

template <int MODE>
__global__ void __launch_bounds__(128, 3) k_mma(
    const float* __restrict__ A,
    const float* __restrict__ Bhi, const float* __restrict__ Blo,
    const float* __restrict__ bias,
    const float* __restrict__ lng, const float* __restrict__ lnb,
    const float* __restrict__ xres,
    float* __restrict__ C, int K, int N)
{
    extern __shared__ float sm[];
    float* AH = sm;
    float* AL = sm + 2*A_BUF;
    float* BH = sm + 4*A_BUF;
    float* BL = sm + 4*A_BUF + 2*B_BUF;

    const int tid  = threadIdx.x;
    const int w    = tid >> 5;
    const int lane = tid & 31;
    const int g    = lane >> 2;       // group id 0..7
    const int tg   = lane & 3;        // thread in group 0..3
    const int mw   = w >> 1;          // M-warp 0..1 (32 rows each)
    const int nw   = w & 1;           // N-warp 0..1 (96 cols each)
    const int bm   = blockIdx.y * 64;
    const int bn   = blockIdx.x * 192;

    // A loads: 2 float4 slots per thread
    int aRow[2], aKq[2];
    const float* aPtr[2];
#pragma unroll
    for (int i = 0; i < 2; i++) {
        int f4 = tid + i * 128;
        aRow[i] = f4 >> 2;
        aKq[i]  = f4 & 3;
        int gm  = bm + aRow[i];
        int gr  = (MODE == 0) ? x_row_of(gm) : gm;
        aPtr[i] = A + (size_t)gr * K + aKq[i] * 4;
    }
    // B cp.async: 6 float4 slots per thread per array
    int bRow[6], bCol[6];
#pragma unroll
    for (int i = 0; i < 6; i++) {
        int f4 = tid + i * 128;
        bRow[i] = f4 / 48;
        bCol[i] = (f4 % 48) * 4;
    }

    // acc[nt][0..3]: rows g, g+8 (cols 2tg,2tg+1); acc[nt][4..7]: rows g+16, g+24
    float acc[12][8];
#pragma unroll
    for (int nt = 0; nt < 12; nt++)
#pragma unroll
        for (int e = 0; e < 8; e++) acc[nt][e] = 0.0f;

    float4 aReg[2];

    auto loadA = [&](int k0) {
#pragma unroll
        for (int i = 0; i < 2; i++)
            aReg[i] = *(const float4*)(aPtr[i] + k0);
    };
    auto storeA = [&](int buf) {
#pragma unroll
        for (int i = 0; i < 2; i++) {
            float4 v = aReg[i];
            float4 h, l;
            h.x = f2tf32(v.x); h.y = f2tf32(v.y); h.z = f2tf32(v.z); h.w = f2tf32(v.w);
            l.x = f2tf32(v.x - h.x); l.y = f2tf32(v.y - h.y);
            l.z = f2tf32(v.z - h.z); l.w = f2tf32(v.w - h.w);
            int off = buf * A_BUF + aRow[i] * AP + aKq[i] * 4;
            *(float4*)(AH + off) = h;
            *(float4*)(AL + off) = l;
        }
    };
    auto issueB = [&](int k0, int buf) {
#pragma unroll
        for (int i = 0; i < 6; i++) {
            int off = buf * B_BUF + bRow[i] * BP + bCol[i];
            size_t gsrc = (size_t)(k0 + bRow[i]) * N + bn + bCol[i];
            cpasync16((uint32_t)__cvta_generic_to_shared(BH + off), Bhi + gsrc);
            cpasync16((uint32_t)__cvta_generic_to_shared(BL + off), Blo + gsrc);
        }
        CP_COMMIT();
    };
    auto compute = [&](int buf) {
        const float* AHb = AH + buf * A_BUF;
        const float* ALb = AL + buf * A_BUF;
        const float* BHb = BH + buf * B_BUF;
        const float* BLb = BL + buf * B_BUF;
#pragma unroll
        for (int ks = 0; ks < 2; ks++) {
            const int kc = ks * 8;
            // A frags: set0 rows mw*32+g, +8; set1 rows +16, +24; cols kc+tg, +4
            uint32_t ah0[4], al0[4], ah1[4], al1[4];
            {
                int r0 = (mw * 32 + g) * AP + kc + tg;
                int r1 = r0 + 8 * AP;
                int r2 = r0 + 16 * AP;
                int r3 = r0 + 24 * AP;
                ah0[0] = __float_as_uint(AHb[r0]);
                ah0[1] = __float_as_uint(AHb[r1]);
                ah0[2] = __float_as_uint(AHb[r0 + 4]);
                ah0[3] = __float_as_uint(AHb[r1 + 4]);
                ah1[0] = __float_as_uint(AHb[r2]);
                ah1[1] = __float_as_uint(AHb[r3]);
                ah1[2] = __float_as_uint(AHb[r2 + 4]);
                ah1[3] = __float_as_uint(AHb[r3 + 4]);
                al0[0] = __float_as_uint(ALb[r0]);
                al0[1] = __float_as_uint(ALb[r1]);
                al0[2] = __float_as_uint(ALb[r0 + 4]);
                al0[3] = __float_as_uint(ALb[r1 + 4]);
                al1[0] = __float_as_uint(ALb[r2]);
                al1[1] = __float_as_uint(ALb[r3]);
                al1[2] = __float_as_uint(ALb[r2 + 4]);
                al1[3] = __float_as_uint(ALb[r3 + 4]);
            }
            const int rk0 = (kc + tg) * BP + nw * 96 + g;
            const int rk1 = rk0 + 4 * BP;
#pragma unroll
            for (int nt = 0; nt < 12; nt++) {
                uint32_t bh0 = __float_as_uint(BHb[rk0 + nt * 8]);
                uint32_t bh1 = __float_as_uint(BHb[rk1 + nt * 8]);
                uint32_t bl0 = __float_as_uint(BLb[rk0 + nt * 8]);
                uint32_t bl1 = __float_as_uint(BLb[rk1 + nt * 8]);
                mma8(acc[nt],     ah0, bh0, bh1);
                mma8(acc[nt] + 4, ah1, bh0, bh1);
                mma8(acc[nt],     al0, bh0, bh1);
                mma8(acc[nt] + 4, al1, bh0, bh1);
                mma8(acc[nt],     ah0, bl0, bl1);
                mma8(acc[nt] + 4, ah1, bl0, bl1);
            }
        }
    };

    // pipeline
    loadA(0);
    issueB(0, 0);
    storeA(0);
    CP_WAIT0();
    __syncthreads();
    int cur = 0;
    for (int k0 = 16; k0 < K; k0 += 16) {
        loadA(k0);
        issueB(k0, cur ^ 1);
        compute(cur);
        storeA(cur ^ 1);
        CP_WAIT0();
        __syncthreads();
        cur ^= 1;
    }
    compute(cur);

    // ---------------- epilogue ----------------
    // lane rows (local): lr_i = mw*32 + g + 8i, i=0..3; acc elems {2i, 2i+1}
    // lane cols (local): cb = nw*96 + nt*8 + 2tg
    const int lrb = mw * 32 + g;

    if (MODE == 0) {
        // +bias; per-row partial sums over this warp's 96 cols (quad shuffle),
        // then cross-warp (nw) combine via smem.
        float s1[4] = {0.f, 0.f, 0.f, 0.f}, s2[4] = {0.f, 0.f, 0.f, 0.f};
#pragma unroll
        for (int nt = 0; nt < 12; nt++) {
            int c = nw * 96 + nt * 8 + 2 * tg;
            float b0 = __ldg(&bias[c]), b1 = __ldg(&bias[c + 1]);
#pragma unroll
            for (int i = 0; i < 4; i++) {
                float v0 = acc[nt][2 * i]     + b0;
                float v1 = acc[nt][2 * i + 1] + b1;
                acc[nt][2 * i]     = v0;
                acc[nt][2 * i + 1] = v1;
                s1[i] += v0 + v1;
                s2[i] += v0 * v0 + v1 * v1;
            }
        }
#pragma unroll
        for (int o = 1; o < 4; o <<= 1) {
#pragma unroll
            for (int i = 0; i < 4; i++) {
                s1[i] += __shfl_xor_sync(0xffffffffu, s1[i], o);
                s2[i] += __shfl_xor_sync(0xffffffffu, s2[i], o);
            }
        }
        __syncthreads();               // smem reuse: all compute reads done
        if (tg == 0) {
#pragma unroll
            for (int i = 0; i < 4; i++) {
                int lr = lrb + 8 * i;
                sm[nw * 64 + lr]        = s1[i];
                sm[128 + nw * 64 + lr]  = s2[i];
            }
        }
        __syncthreads();
        float mu[4], inv[4];
#pragma unroll
        for (int i = 0; i < 4; i++) {
            int lr = lrb + 8 * i;
            float S1 = sm[lr] + sm[64 + lr];
            float S2 = sm[128 + lr] + sm[192 + lr];
            mu[i]  = S1 * (1.0f / 192.0f);
            inv[i] = rsqrtf(S2 * (1.0f / 192.0f) - mu[i] * mu[i] + 1e-5f);
        }
#pragma unroll
        for (int nt = 0; nt < 12; nt++) {
            int c = nw * 96 + nt * 8 + 2 * tg;
            float gg0 = __ldg(&lng[c]), gg1 = __ldg(&lng[c + 1]);
            float bb0 = __ldg(&lnb[c]), bb1 = __ldg(&lnb[c + 1]);
#pragma unroll
            for (int i = 0; i < 4; i++) {
                int mr = bm + lrb + 8 * i;
                float2 o2 = make_float2(
                    (acc[nt][2 * i]     - mu[i]) * inv[i] * gg0 + bb0,
                    (acc[nt][2 * i + 1] - mu[i]) * inv[i] * gg1 + bb1);
                *(float2*)(C + (size_t)mr * N + c) = o2;
            }
        }
    } else if (MODE == 1 || MODE == 2) {
        const float* ct = (MODE == 1) ? g_cos_u : g_cos_d;
        const float* st = (MODE == 1) ? g_sin_u : g_sin_d;
#pragma unroll
        for (int nt = 0; nt < 12; nt++) {
            int c = nw * 96 + nt * 8 + 2 * tg;
            int p = (c >> 1);
#pragma unroll
            for (int i = 0; i < 4; i++) {
                int lr = lrb + 8 * i;
                int t  = lr & 31;              // bm, mw*32 multiples of 32
                float cc = ct[t * HALF + p], ss = st[t * HALF + p];
                float e = acc[nt][2 * i], od = acc[nt][2 * i + 1];
                *(float2*)(C + (size_t)(bm + lr) * N + c) =
                    make_float2(e * cc - od * ss, od * cc + e * ss);
            }
        }
    } else if (MODE == 3) {
#pragma unroll
        for (int nt = 0; nt < 12; nt++) {
            int c = nw * 96 + nt * 8 + 2 * tg;
#pragma unroll
            for (int i = 0; i < 4; i++) {
                int mr = bm + lrb + 8 * i;
                *(float2*)(C + (size_t)mr * N + c) =
                    make_float2(acc[nt][2 * i], acc[nt][2 * i + 1]);
            }
        }
    } else { // MODE 4: +bias +residual, gathered rows
        int grr[4];
#pragma unroll
        for (int i = 0; i < 4; i++) grr[i] = x_row_of(bm + lrb + 8 * i);
#pragma unroll
        for (int nt = 0; nt < 12; nt++) {
            int c = bn + nw * 96 + nt * 8 + 2 * tg;
            float b0 = __ldg(&bias[c]), b1 = __ldg(&bias[c + 1]);
#pragma unroll
            for (int i = 0; i < 4; i++) {
                float2 xv = *(const float2*)(xres + (size_t)grr[i] * N + c);
                *(float2*)(C + (size_t)grr[i] * N + c) =
                    make_float2(acc[nt][2 * i] + b0 + xv.x,
                                acc[nt][2 * i + 1] + b1 + xv.y);
            }
        }
    }
}

// ---------------- per-sequence retention attention -------------------------
__global__ void __launch_bounds__(256) k_attn(
    const float* __restrict__ Q, const float* __restrict__ Kmat,
    const float* __restrict__ V, float* __restrict__ R)
{
    __shared__ __align__(16) float sKV[SEQ][DH];
    const int q   = blockIdx.x;
    const int tid = threadIdx.x;
    const int n   = tid >> 3;
    const int j   = tid & 7;
    const size_t base = (size_t)q * SEQ * DH;

    for (int i = tid; i < SEQ * DH / 4; i += 256)
        ((float4*)&sKV[0][0])[i] = ((const float4*)(Kmat + base))[i];

    float qr[24];
    const float* qp = Q + base + (size_t)n * DH + j * 24;
#pragma unroll
    for (int dd = 0; dd < 6; dd++)
        *(float4*)&qr[dd * 4] = *(const float4*)(qp + dd * 4);
    __syncthreads();

    float att[SEQ];
#pragma unroll
    for (int m = 0; m < SEQ; m++) {
        float s = 0.0f;
#pragma unroll
        for (int dd = 0; dd < 6; dd++) {
            float4 kv = *(const float4*)&sKV[m][j * 24 + dd * 4];
            s += qr[dd*4+0]*kv.x + qr[dd*4+1]*kv.y + qr[dd*4+2]*kv.z + qr[dd*4+3]*kv.w;
        }
        att[m] = s;
    }
#pragma unroll
    for (int m = 0; m < SEQ; m++) {
#pragma unroll
        for (int o = 1; o < 8; o <<= 1)
            att[m] += __shfl_xor_sync(0xffffffffu, att[m], o);
        att[m] = (n >= m) ? ldexpf(att[m], m - n) : 0.0f;
    }

    __syncthreads();
    for (int i = tid; i < SEQ * DH / 4; i += 256)
        ((float4*)&sKV[0][0])[i] = ((const float4*)(V + base))[i];
    __syncthreads();

    float acc[24];
#pragma unroll
    for (int dd = 0; dd < 24; dd++) acc[dd] = 0.0f;
#pragma unroll
    for (int m = 0; m < SEQ; m++) {
        float a = att[m];
#pragma unroll
        for (int dd = 0; dd < 6; dd++) {
            float4 vv = *(const float4*)&sKV[m][j * 24 + dd * 4];
            acc[dd*4+0] += a * vv.x; acc[dd*4+1] += a * vv.y;
            acc[dd*4+2] += a * vv.z; acc[dd*4+3] += a * vv.w;
        }
    }
    float* rp = R + base + (size_t)n * DH + j * 24;
#pragma unroll
    for (int dd = 0; dd < 6; dd++)
        *(float4*)(rp + dd * 4) = *(const float4*)&acc[dd * 4];
}

// ---------------- launch --------------------------------------------------
extern "C" void kernel_launch(void* const* d_in, const int* in_sizes, int n_in,
                              void* d_out, int out_size)
{
    const float* x    = (const float*)d_in[0];
    const float* W1   = (const float*)d_in[1];
    const float* b1   = (const float*)d_in[2];
    const float* W2   = (const float*)d_in[3];
    const float* b2   = (const float*)d_in[4];
    const float* ln_g = (const float*)d_in[5];
    const float* ln_b = (const float*)d_in[6];
    const float* WQ   = (const float*)d_in[7];
    const float* WK   = (const float*)d_in[8];
    const float* WV   = (const float*)d_in[9];
    float* out = (float*)d_out;

    float* xd = nullptr; cudaGetSymbolAddress((void**)&xd, g_xd);
    float* qb = nullptr; cudaGetSymbolAddress((void**)&qb, g_q);
    float* kb = nullptr; cudaGetSymbolAddress((void**)&kb, g_k);
    float* vb = nullptr; cudaGetSymbolAddress((void**)&vb, g_v);
    float* rb = nullptr; cudaGetSymbolAddress((void**)&rb, g_ret);
    float *w1h, *w1l, *wqh, *wql, *wkh, *wkl, *wvh, *wvl, *w2h, *w2l;
    cudaGetSymbolAddress((void**)&w1h, g_w1h); cudaGetSymbolAddress((void**)&w1l, g_w1l);
    cudaGetSymbolAddress((void**)&wqh, g_wqh); cudaGetSymbolAddress((void**)&wql, g_wql);
    cudaGetSymbolAddress((void**)&wkh, g_wkh); cudaGetSymbolAddress((void**)&wkl, g_wkl);
    cudaGetSymbolAddress((void**)&wvh, g_wvh); cudaGetSymbolAddress((void**)&wvl, g_wvl);
    cudaGetSymbolAddress((void**)&w2h, g_w2h); cudaGetSymbolAddress((void**)&w2l, g_w2l);

    const int SMEM_BYTES = SMEM_FLOATS * 4;   // 71680
    cudaFuncSetAttribute(k_mma<0>, cudaFuncAttributeMaxDynamicSharedMemorySize, SMEM_BYTES);
    cudaFuncSetAttribute(k_mma<1>, cudaFuncAttributeMaxDynamicSharedMemorySize, SMEM_BYTES);
    cudaFuncSetAttribute(k_mma<2>, cudaFuncAttributeMaxDynamicSharedMemorySize, SMEM_BYTES);
    cudaFuncSetAttribute(k_mma<3>, cudaFuncAttributeMaxDynamicSharedMemorySize, SMEM_BYTES);
    cudaFuncSetAttribute(k_mma<4>, cudaFuncAttributeMaxDynamicSharedMemorySize, SMEM_BYTES);

    // prep: weight tf32 split + xPos tables
    {
        int total = DD*DH + 3*DH*DH + DH*DD + SEQ*HALF;
        k_prep<<<(total + 255) / 256, 256>>>(W1, WQ, WK, WV, W2);
    }

    // GEMM1 + bias + fused LN: x(gathered) @ W1 -> g_xd  [M=50176, K=768, N=192]
    k_mma<0><<<dim3(1, MTOT / 64), 128, SMEM_BYTES>>>(x, w1h, w1l, b1, ln_g, ln_b, nullptr, xd, DD, DH);
    // QKV: h @ W{Q,K,V}  [K=192, N=192], xPos fused for Q/K
    k_mma<1><<<dim3(1, MTOT / 64), 128, SMEM_BYTES>>>(xd, wqh, wql, nullptr, nullptr, nullptr, nullptr, qb, DH, DH);
    k_mma<2><<<dim3(1, MTOT / 64), 128, SMEM_BYTES>>>(xd, wkh, wkl, nullptr, nullptr, nullptr, nullptr, kb, DH, DH);
    k_mma<3><<<dim3(1, MTOT / 64), 128, SMEM_BYTES>>>(xd, wvh, wvl, nullptr, nullptr, nullptr, nullptr, vb, DH, DH);
    k_attn<<<NSEQ, 256>>>(qb, kb, vb, rb);
    // GEMM2: ret @ W2 + b2 + x (residual) -> d_out  [K=192, N=768]
    k_mma<4><<<dim3(DD / 192, MTOT / 64), 128, SMEM_BYTES>>>(rb, w2h, w2l, b2, nullptr, nullptr, x, out, DH, DD);
}

// round 13
// speedup vs baseline: 1.3005x; 1.3005x over previous
#include <cuda_runtime.h>
#include <cuda_fp16.h>
#include <cstdint>

// ---------------- problem constants ----------------
#define HW   196
#define BB   8
#define SEQ  32
#define DD   768
#define DH   192
#define HALF 96                  // DH/2
#define NSEQ (BB*HW)             // 1568
#define MTOT (NSEQ*SEQ)          // 50176

// ---------------- scratch (__device__ globals) ------------------------------
__device__ float g_xd [MTOT*DH];
__device__ float g_q  [MTOT*DH];
__device__ float g_k  [MTOT*DH];
__device__ float g_v  [MTOT*DH];
__device__ float g_ret[MTOT*DH];

// fp16-split weights, TRANSPOSED [N][K] layout
__device__ __half g_w1h[DH*DD], g_w1l[DH*DD];     // [192][768]
__device__ __half g_wqh[DH*DH], g_wql[DH*DH];     // [192][192]
__device__ __half g_wkh[DH*DH], g_wkl[DH*DH];
__device__ __half g_wvh[DH*DH], g_wvl[DH*DH];
__device__ __half g_w2h[DD*DH], g_w2l[DD*DH];     // [768][192]

// xPos tables: [t (0..31)][p (0..95)]
__device__ float g_cos_u[SEQ*HALF];
__device__ float g_sin_u[SEQ*HALF];
__device__ float g_cos_d[SEQ*HALF];
__device__ float g_sin_d[SEQ*HALF];

__device__ __forceinline__ int x_row_of(int m) {
    int q  = m >> 5;
    int t  = m & 31;
    int bi = q / HW;
    int hi = q - bi * HW;
    return hi * (BB * SEQ) + bi * SEQ + t;
}

// ---------------- helpers ----------------------------------------------------
__device__ __forceinline__ void cpasync16(uint32_t s, const void* g) {
    asm volatile("cp.async.ca.shared.global [%0], [%1], 16;" :: "r"(s), "l"(g) : "memory");
}
#define CP_COMMIT() asm volatile("cp.async.commit_group;" ::: "memory")
#define CP_WAIT0()  asm volatile("cp.async.wait_group 0;" ::: "memory")

// m16n8k16 fp16 MMA, fp32 accumulate in place
__device__ __forceinline__ void mma16(float* d, const uint32_t* a, uint32_t b0, uint32_t b1) {
    asm volatile(
        "mma.sync.aligned.m16n8k16.row.col.f32.f16.f16.f32 "
        "{%0,%1,%2,%3}, {%4,%5,%6,%7}, {%8,%9}, {%0,%1,%2,%3};"
        : "+f"(d[0]), "+f"(d[1]), "+f"(d[2]), "+f"(d[3])
        : "r"(a[0]), "r"(a[1]), "r"(a[2]), "r"(a[3]), "r"(b0), "r"(b1));
}

// ---------------- prep: weight fp16 split + transpose + xPos tables ---------
__device__ __forceinline__ void w_split_t(const float* __restrict__ W,
                                          __half* __restrict__ Wh, __half* __restrict__ Wl,
                                          int idx, int K, int N) {
    int k = idx / N, n = idx - k * N;
    float v = W[idx];
    __half h = __float2half_rn(v);
    __half l = __float2half_rn(v - __half2float(h));
    Wh[(size_t)n * K + k] = h;
    Wl[(size_t)n * K + k] = l;
}

__global__ void k_prep(const float* __restrict__ W1, const float* __restrict__ WQ,
                       const float* __restrict__ WK, const float* __restrict__ WV,
                       const float* __restrict__ W2) {
    int idx = blockIdx.x * blockDim.x + threadIdx.x;
    if (idx < DD*DH) { w_split_t(W1, g_w1h, g_w1l, idx, DD, DH); return; }
    idx -= DD*DH;
    if (idx < DH*DH) { w_split_t(WQ, g_wqh, g_wql, idx, DH, DH); return; }
    idx -= DH*DH;
    if (idx < DH*DH) { w_split_t(WK, g_wkh, g_wkl, idx, DH, DH); return; }
    idx -= DH*DH;
    if (idx < DH*DH) { w_split_t(WV, g_wvh, g_wvl, idx, DH, DH); return; }
    idx -= DH*DH;
    if (idx < DH*DD) { w_split_t(W2, g_w2h, g_w2l, idx, DH, DD); return; }
    idx -= DH*DD;
    if (idx < SEQ*HALF) {
        int t = idx / HALF, p = idx % HALF;
        double base = (2.0 * p + 0.4 * (double)DH) / (1.4 * (double)DH);
        double sc_u = pow(base, (double)t / 512.0);
        double sc_d = 1.0 / sc_u;
        double invf = pow(10000.0, -(double)p / (double)HALF);
        double ang  = (double)t * invf;
        double s = sin(ang), c = cos(ang);
        g_cos_u[idx] = (float)(c * sc_u);
        g_sin_u[idx] = (float)(s * sc_u);
        g_cos_d[idx] = (float)(c * sc_d);
        g_sin_d[idx] = (float)(s * sc_d);
    }
}

// ---------------- fp16x3 mma.sync GEMM, BM=64 BN=192 BK=16 ------------------
// 128 threads = 4 warps (2M x 2N); warp tile 32 rows x 96 cols.
// m16n8k16: K=16 per HMMA -> 72 HMMA / warp / ktile (was 144 with tf32 k8).
// Smem pitch 48B (12 u32) per 16-k row: conflict-free frag LDS + 16B-aligned cp.async.
// MODE 0: A gathered from x; +bias then fused LayerNorm (cross-warp smem red.)
// MODE 1/2: xPos up/down epilogue   MODE 3: plain
// MODE 4: +bias +x residual (gathered rows), gathered store
#define A_B32 (64*12)             // 768 u32 per A buffer
#define B_B32 (192*12)            // 2304 u32 per B buffer
#define SMEM_U32 (4*A_B32 + 4*B_B32)   // 12288 u32 = 49152 B

template <int MODE>
__global__ void __launch_bounds__(128, 3) k_mma(
    const float* __restrict__ A,
    const __half* __restrict__ Bhi, const __half* __restrict__ Blo,
    const float* __restrict__ bias,
    const float* __restrict__ lng, const float* __restrict__ lnb,
    const float* __restrict__ xres,
    float* __restrict__ C, int K, int N)
{
    extern __shared__ uint32_t smu[];
    uint32_t* AH = smu;
    uint32_t* AL = smu + 2*A_B32;
    uint32_t* BH = smu + 4*A_B32;
    uint32_t* BL = smu + 4*A_B32 + 2*B_B32;

    const int tid  = threadIdx.x;
    const int w    = tid >> 5;
    const int lane = tid & 31;
    const int g    = lane >> 2;       // group id 0..7
    const int tg   = lane & 3;        // thread in group 0..3
    const int mw   = w >> 1;          // M-warp 0..1 (32 rows)
    const int nw   = w & 1;           // N-warp 0..1 (96 cols)
    const int bm   = blockIdx.y * 64;
    const int bn   = blockIdx.x * 192;

    // A loads: 2 float4 slots per thread
    int aRow[2], aKq[2];
    const float* aPtr[2];
#pragma unroll
    for (int i = 0; i < 2; i++) {
        int f4 = tid + i * 128;
        aRow[i] = f4 >> 2;
        aKq[i]  = f4 & 3;
        int gm  = bm + aRow[i];
        int gr  = (MODE == 0) ? x_row_of(gm) : gm;
        aPtr[i] = A + (size_t)gr * K + aKq[i] * 4;
    }
    // B cp.async slots: 768 16B-chunks (2 arrays x 192 rows x 2 chunks) / 128 thr = 6
    int bArr[6], bN[6], bC[6];
#pragma unroll
    for (int i = 0; i < 6; i++) {
        int f = tid + i * 128;
        bArr[i] = f / 384;
        int r = f % 384;
        bN[i] = r >> 1;
        bC[i] = r & 1;
    }

    // acc[nt][0..3]: rows g,g+8 cols {2tg,2tg+1}; acc[nt][4..7]: rows g+16,g+24
    float acc[12][8];
#pragma unroll
    for (int nt = 0; nt < 12; nt++)
#pragma unroll
        for (int e = 0; e < 8; e++) acc[nt][e] = 0.0f;

    float4 aReg[2];

    auto loadA = [&](int k0) {
#pragma unroll
        for (int i = 0; i < 2; i++)
            aReg[i] = *(const float4*)(aPtr[i] + k0);
    };
    auto storeA = [&](int buf) {
#pragma unroll
        for (int i = 0; i < 2; i++) {
            float4 v = aReg[i];
            __half hx = __float2half_rn(v.x), hy = __float2half_rn(v.y);
            __half hz = __float2half_rn(v.z), hw = __float2half_rn(v.w);
            __half lx = __float2half_rn(v.x - __half2float(hx));
            __half ly = __float2half_rn(v.y - __half2float(hy));
            __half lz = __float2half_rn(v.z - __half2float(hz));
            __half lw = __float2half_rn(v.w - __half2float(hw));
            __half2 h0 = __halves2half2(hx, hy), h1 = __halves2half2(hz, hw);
            __half2 l0 = __halves2half2(lx, ly), l1 = __halves2half2(lz, lw);
            int base = buf * A_B32 + aRow[i] * 12 + aKq[i] * 2;
            AH[base]     = *(uint32_t*)&h0;
            AH[base + 1] = *(uint32_t*)&h1;
            AL[base]     = *(uint32_t*)&l0;
            AL[base + 1] = *(uint32_t*)&l1;
        }
    };
    auto issueB = [&](int k0, int buf) {
#pragma unroll
        for (int i = 0; i < 6; i++) {
            const __half* src = (bArr[i] ? Blo : Bhi)
                              + (size_t)(bn + bN[i]) * K + k0 + bC[i] * 8;
            uint32_t* dstA = bArr[i] ? BL : BH;
            uint32_t dst = (uint32_t)__cvta_generic_to_shared(
                dstA + buf * B_B32 + bN[i] * 12 + bC[i] * 4);
            cpasync16(dst, src);
        }
        CP_COMMIT();
    };
    auto compute = [&](int buf) {
        const uint32_t* AHb = AH + buf * A_B32;
        const uint32_t* ALb = AL + buf * A_B32;
        const uint32_t* BHb = BH + buf * B_B32;
        const uint32_t* BLb = BL + buf * B_B32;
        const int ra = (mw * 32 + g) * 12 + tg;
        uint32_t ah0[4] = {AHb[ra],       AHb[ra + 96],  AHb[ra + 4],   AHb[ra + 100]};
        uint32_t ah1[4] = {AHb[ra + 192], AHb[ra + 288], AHb[ra + 196], AHb[ra + 292]};
        uint32_t al0[4] = {ALb[ra],       ALb[ra + 96],  ALb[ra + 4],   ALb[ra + 100]};
        uint32_t al1[4] = {ALb[ra + 192], ALb[ra + 288], ALb[ra + 196], ALb[ra + 292]};
#pragma unroll
        for (int nt = 0; nt < 12; nt++) {
            int rb = (nw * 96 + nt * 8 + g) * 12 + tg;
            uint32_t bh0 = BHb[rb], bh1 = BHb[rb + 4];
            uint32_t bl0 = BLb[rb], bl1 = BLb[rb + 4];
            mma16(acc[nt],     ah0, bh0, bh1);
            mma16(acc[nt] + 4, ah1, bh0, bh1);
            mma16(acc[nt],     al0, bh0, bh1);
            mma16(acc[nt] + 4, al1, bh0, bh1);
            mma16(acc[nt],     ah0, bl0, bl1);
            mma16(acc[nt] + 4, ah1, bl0, bl1);
        }
    };

    // pipeline
    loadA(0);
    issueB(0, 0);
    storeA(0);
    CP_WAIT0();
    __syncthreads();
    int cur = 0;
    for (int k0 = 16; k0 < K; k0 += 16) {
        loadA(k0);
        issueB(k0, cur ^ 1);
        compute(cur);
        storeA(cur ^ 1);
        CP_WAIT0();
        __syncthreads();
        cur ^= 1;
    }
    compute(cur);

    // ---------------- epilogue ----------------
    const int lrb = mw * 32 + g;

    if (MODE == 0) {
        float* smf = (float*)smu;     // reuse smem for LN cross-warp reduction
        float s1[4] = {0.f, 0.f, 0.f, 0.f}, s2[4] = {0.f, 0.f, 0.f, 0.f};
#pragma unroll
        for (int nt = 0; nt < 12; nt++) {
            int c = nw * 96 + nt * 8 + 2 * tg;
            float b0 = __ldg(&bias[c]), b1 = __ldg(&bias[c + 1]);
#pragma unroll
            for (int i = 0; i < 4; i++) {
                float v0 = acc[nt][2 * i]     + b0;
                float v1 = acc[nt][2 * i + 1] + b1;
                acc[nt][2 * i]     = v0;
                acc[nt][2 * i + 1] = v1;
                s1[i] += v0 + v1;
                s2[i] += v0 * v0 + v1 * v1;
            }
        }
#pragma unroll
        for (int o = 1; o < 4; o <<= 1) {
#pragma unroll
            for (int i = 0; i < 4; i++) {
                s1[i] += __shfl_xor_sync(0xffffffffu, s1[i], o);
                s2[i] += __shfl_xor_sync(0xffffffffu, s2[i], o);
            }
        }
        __syncthreads();
        if (tg == 0) {
#pragma unroll
            for (int i = 0; i < 4; i++) {
                int lr = lrb + 8 * i;
                smf[nw * 64 + lr]       = s1[i];
                smf[128 + nw * 64 + lr] = s2[i];
            }
        }
        __syncthreads();
        float mu[4], inv[4];
#pragma unroll
        for (int i = 0; i < 4; i++) {
            int lr = lrb + 8 * i;
            float S1 = smf[lr] + smf[64 + lr];
            float S2 = smf[128 + lr] + smf[192 + lr];
            mu[i]  = S1 * (1.0f / 192.0f);
            inv[i] = rsqrtf(S2 * (1.0f / 192.0f) - mu[i] * mu[i] + 1e-5f);
        }
#pragma unroll
        for (int nt = 0; nt < 12; nt++) {
            int c = nw * 96 + nt * 8 + 2 * tg;
            float gg0 = __ldg(&lng[c]), gg1 = __ldg(&lng[c + 1]);
            float bb0 = __ldg(&lnb[c]), bb1 = __ldg(&lnb[c + 1]);
#pragma unroll
            for (int i = 0; i < 4; i++) {
                int mr = bm + lrb + 8 * i;
                float2 o2 = make_float2(
                    (acc[nt][2 * i]     - mu[i]) * inv[i] * gg0 + bb0,
                    (acc[nt][2 * i + 1] - mu[i]) * inv[i] * gg1 + bb1);
                *(float2*)(C + (size_t)mr * N + c) = o2;
            }
        }
    } else if (MODE == 1 || MODE == 2) {
        const float* ct = (MODE == 1) ? g_cos_u : g_cos_d;
        const float* st = (MODE == 1) ? g_sin_u : g_sin_d;
#pragma unroll
        for (int nt = 0; nt < 12; nt++) {
            int c = nw * 96 + nt * 8 + 2 * tg;
            int p = (c >> 1);
#pragma unroll
            for (int i = 0; i < 4; i++) {
                int lr = lrb + 8 * i;
                int t  = lr & 31;
                float cc = ct[t * HALF + p], ss = st[t * HALF + p];
                float e = acc[nt][2 * i], od = acc[nt][2 * i + 1];
                *(float2*)(C + (size_t)(bm + lr) * N + c) =
                    make_float2(e * cc - od * ss, od * cc + e * ss);
            }
        }
    } else if (MODE == 3) {
#pragma unroll
        for (int nt = 0; nt < 12; nt++) {
            int c = nw * 96 + nt * 8 + 2 * tg;
#pragma unroll
            for (int i = 0; i < 4; i++) {
                int mr = bm + lrb + 8 * i;
                *(float2*)(C + (size_t)mr * N + c) =
                    make_float2(acc[nt][2 * i], acc[nt][2 * i + 1]);
            }
        }
    } else { // MODE 4: +bias +residual, gathered rows
        int grr[4];
#pragma unroll
        for (int i = 0; i < 4; i++) grr[i] = x_row_of(bm + lrb + 8 * i);
#pragma unroll
        for (int nt = 0; nt < 12; nt++) {
            int c = bn + nw * 96 + nt * 8 + 2 * tg;
            float b0 = __ldg(&bias[c]), b1 = __ldg(&bias[c + 1]);
#pragma unroll
            for (int i = 0; i < 4; i++) {
                float2 xv = *(const float2*)(xres + (size_t)grr[i] * N + c);
                *(float2*)(C + (size_t)grr[i] * N + c) =
                    make_float2(acc[nt][2 * i] + b0 + xv.x,
                                acc[nt][2 * i + 1] + b1 + xv.y);
            }
        }
    }
}

// ---------------- per-sequence retention attention -------------------------
__global__ void __launch_bounds__(256) k_attn(
    const float* __restrict__ Q, const float* __restrict__ Kmat,
    const float* __restrict__ V, float* __restrict__ R)
{
    __shared__ __align__(16) float sKV[SEQ][DH];
    const int q   = blockIdx.x;
    const int tid = threadIdx.x;
    const int n   = tid >> 3;
    const int j   = tid & 7;
    const size_t base = (size_t)q * SEQ * DH;

    for (int i = tid; i < SEQ * DH / 4; i += 256)
        ((float4*)&sKV[0][0])[i] = ((const float4*)(Kmat + base))[i];

    float qr[24];
    const float* qp = Q + base + (size_t)n * DH + j * 24;
#pragma unroll
    for (int dd = 0; dd < 6; dd++)
        *(float4*)&qr[dd * 4] = *(const float4*)(qp + dd * 4);
    __syncthreads();

    float att[SEQ];
#pragma unroll
    for (int m = 0; m < SEQ; m++) {
        float s = 0.0f;
#pragma unroll
        for (int dd = 0; dd < 6; dd++) {
            float4 kv = *(const float4*)&sKV[m][j * 24 + dd * 4];
            s += qr[dd*4+0]*kv.x + qr[dd*4+1]*kv.y + qr[dd*4+2]*kv.z + qr[dd*4+3]*kv.w;
        }
        att[m] = s;
    }
#pragma unroll
    for (int m = 0; m < SEQ; m++) {
#pragma unroll
        for (int o = 1; o < 8; o <<= 1)
            att[m] += __shfl_xor_sync(0xffffffffu, att[m], o);
        att[m] = (n >= m) ? ldexpf(att[m], m - n) : 0.0f;
    }

    __syncthreads();
    for (int i = tid; i < SEQ * DH / 4; i += 256)
        ((float4*)&sKV[0][0])[i] = ((const float4*)(V + base))[i];
    __syncthreads();

    float acc[24];
#pragma unroll
    for (int dd = 0; dd < 24; dd++) acc[dd] = 0.0f;
#pragma unroll
    for (int m = 0; m < SEQ; m++) {
        float a = att[m];
#pragma unroll
        for (int dd = 0; dd < 6; dd++) {
            float4 vv = *(const float4*)&sKV[m][j * 24 + dd * 4];
            acc[dd*4+0] += a * vv.x; acc[dd*4+1] += a * vv.y;
            acc[dd*4+2] += a * vv.z; acc[dd*4+3] += a * vv.w;
        }
    }
    float* rp = R + base + (size_t)n * DH + j * 24;
#pragma unroll
    for (int dd = 0; dd < 6; dd++)
        *(float4*)(rp + dd * 4) = *(const float4*)&acc[dd * 4];
}

// ---------------- launch --------------------------------------------------
extern "C" void kernel_launch(void* const* d_in, const int* in_sizes, int n_in,
                              void* d_out, int out_size)
{
    const float* x    = (const float*)d_in[0];
    const float* W1   = (const float*)d_in[1];
    const float* b1   = (const float*)d_in[2];
    const float* W2   = (const float*)d_in[3];
    const float* b2   = (const float*)d_in[4];
    const float* ln_g = (const float*)d_in[5];
    const float* ln_b = (const float*)d_in[6];
    const float* WQ   = (const float*)d_in[7];
    const float* WK   = (const float*)d_in[8];
    const float* WV   = (const float*)d_in[9];
    float* out = (float*)d_out;

    float* xd = nullptr; cudaGetSymbolAddress((void**)&xd, g_xd);
    float* qb = nullptr; cudaGetSymbolAddress((void**)&qb, g_q);
    float* kb = nullptr; cudaGetSymbolAddress((void**)&kb, g_k);
    float* vb = nullptr; cudaGetSymbolAddress((void**)&vb, g_v);
    float* rb = nullptr; cudaGetSymbolAddress((void**)&rb, g_ret);
    __half *w1h, *w1l, *wqh, *wql, *wkh, *wkl, *wvh, *wvl, *w2h, *w2l;
    cudaGetSymbolAddress((void**)&w1h, g_w1h); cudaGetSymbolAddress((void**)&w1l, g_w1l);
    cudaGetSymbolAddress((void**)&wqh, g_wqh); cudaGetSymbolAddress((void**)&wql, g_wql);
    cudaGetSymbolAddress((void**)&wkh, g_wkh); cudaGetSymbolAddress((void**)&wkl, g_wkl);
    cudaGetSymbolAddress((void**)&wvh, g_wvh); cudaGetSymbolAddress((void**)&wvl, g_wvl);
    cudaGetSymbolAddress((void**)&w2h, g_w2h); cudaGetSymbolAddress((void**)&w2l, g_w2l);

    const int SMEM_BYTES = SMEM_U32 * 4;   // 49152
    cudaFuncSetAttribute(k_mma<0>, cudaFuncAttributeMaxDynamicSharedMemorySize, SMEM_BYTES);
    cudaFuncSetAttribute(k_mma<1>, cudaFuncAttributeMaxDynamicSharedMemorySize, SMEM_BYTES);
    cudaFuncSetAttribute(k_mma<2>, cudaFuncAttributeMaxDynamicSharedMemorySize, SMEM_BYTES);
    cudaFuncSetAttribute(k_mma<3>, cudaFuncAttributeMaxDynamicSharedMemorySize, SMEM_BYTES);
    cudaFuncSetAttribute(k_mma<4>, cudaFuncAttributeMaxDynamicSharedMemorySize, SMEM_BYTES);

    // prep: weight fp16 split + transpose + xPos tables
    {
        int total = DD*DH + 3*DH*DH + DH*DD + SEQ*HALF;
        k_prep<<<(total + 255) / 256, 256>>>(W1, WQ, WK, WV, W2);
    }

    // GEMM1 + bias + fused LN: x(gathered) @ W1 -> g_xd  [M=50176, K=768, N=192]
    k_mma<0><<<dim3(1, MTOT / 64), 128, SMEM_BYTES>>>(x, w1h, w1l, b1, ln_g, ln_b, nullptr, xd, DD, DH);
    // QKV: h @ W{Q,K,V}  [K=192, N=192], xPos fused for Q/K
    k_mma<1><<<dim3(1, MTOT / 64), 128, SMEM_BYTES>>>(xd, wqh, wql, nullptr, nullptr, nullptr, nullptr, qb, DH, DH);
    k_mma<2><<<dim3(1, MTOT / 64), 128, SMEM_BYTES>>>(xd, wkh, wkl, nullptr, nullptr, nullptr, nullptr, kb, DH, DH);
    k_mma<3><<<dim3(1, MTOT / 64), 128, SMEM_BYTES>>>(xd, wvh, wvl, nullptr, nullptr, nullptr, nullptr, vb, DH, DH);
    k_attn<<<NSEQ, 256>>>(qb, kb, vb, rb);
    // GEMM2: ret @ W2 + b2 + x (residual) -> d_out  [K=192, N=768]
    k_mma<4><<<dim3(DD / 192, MTOT / 64), 128, SMEM_BYTES>>>(rb, w2h, w2l, b2, nullptr, nullptr, x, out, DH, DD);
}